// round 1
// baseline (speedup 1.0000x reference)
#include <cuda_runtime.h>
#include <math.h>

// Problem constants (fixed shapes for this benchmark)
#define BSZ 2
#define LSEQ 2048
#define DMODEL 512
#define NHEAD 8
#define EDIM 64
#define NTOK 64
#define NVAR 32

// ---------------- scratch (device globals; no allocation allowed) ----------
__device__ float g_Q[BSZ * NHEAD * LSEQ * EDIM];   // [b][h][l][e]
__device__ float g_K[BSZ * NHEAD * LSEQ * EDIM];
__device__ float g_V[BSZ * NHEAD * LSEQ * EDIM];
__device__ float g_VO[BSZ * LSEQ * DMODEL];        // attention out, (B*L, D)
__device__ float g_part[BSZ * NHEAD * 32 * 64 * 64]; // partial accumulators
__device__ float g_ml[BSZ * NHEAD * 32 * 64 * 2];    // (m, l) per partial row

// ---------------- fused QKV projection GEMM --------------------------------
// C[m,n] = sum_k x[m,k] * W[n,k] + b[n]; writes to [b][h][l][e] layout.
#define BM 128
#define BN 128
#define BKK 16

__global__ __launch_bounds__(256) void gemm_qkv(
    const float* __restrict__ x,
    const float* __restrict__ Wq, const float* __restrict__ bq,
    const float* __restrict__ Wk, const float* __restrict__ bk,
    const float* __restrict__ Wv, const float* __restrict__ bv)
{
    __shared__ float As[BKK][BM + 4];
    __shared__ float Bs[BKK][BN + 4];

    const int tid = threadIdx.x;
    const int m0 = blockIdx.y * BM;
    const int n0 = blockIdx.x * BN;      // 0..1535
    const int which = n0 >> 9;           // 0:q 1:k 2:v (BN divides 512)
    const int wn0 = n0 & 511;

    const float* W  = (which == 0) ? Wq : (which == 1) ? Wk : Wv;
    const float* bi = (which == 0) ? bq : (which == 1) ? bk : bv;
    float* dst      = (which == 0) ? g_Q : (which == 1) ? g_K : g_V;

    const int ty = tid >> 4, tx = tid & 15;

    float acc[8][8];
#pragma unroll
    for (int i = 0; i < 8; i++)
#pragma unroll
        for (int jj = 0; jj < 8; jj++) acc[i][jj] = 0.f;

    int rowi[2], c4o[2];
#pragma unroll
    for (int ff = 0; ff < 2; ff++) {
        int f = tid + ff * 256;
        rowi[ff] = f >> 2;
        c4o[ff] = (f & 3) << 2;
    }

    // prime prefetch
    float4 pa[2], pb[2];
#pragma unroll
    for (int ff = 0; ff < 2; ff++) {
        pa[ff] = *(const float4*)(x + (size_t)(m0 + rowi[ff]) * DMODEL + c4o[ff]);
        pb[ff] = *(const float4*)(W + (size_t)(wn0 + rowi[ff]) * DMODEL + c4o[ff]);
    }

    for (int kt = 0; kt < DMODEL; kt += BKK) {
#pragma unroll
        for (int ff = 0; ff < 2; ff++) {
            int c4 = c4o[ff], rw = rowi[ff];
            As[c4 + 0][rw] = pa[ff].x; As[c4 + 1][rw] = pa[ff].y;
            As[c4 + 2][rw] = pa[ff].z; As[c4 + 3][rw] = pa[ff].w;
            Bs[c4 + 0][rw] = pb[ff].x; Bs[c4 + 1][rw] = pb[ff].y;
            Bs[c4 + 2][rw] = pb[ff].z; Bs[c4 + 3][rw] = pb[ff].w;
        }
        __syncthreads();
        if (kt + BKK < DMODEL) {
#pragma unroll
            for (int ff = 0; ff < 2; ff++) {
                pa[ff] = *(const float4*)(x + (size_t)(m0 + rowi[ff]) * DMODEL + kt + BKK + c4o[ff]);
                pb[ff] = *(const float4*)(W + (size_t)(wn0 + rowi[ff]) * DMODEL + kt + BKK + c4o[ff]);
            }
        }
#pragma unroll
        for (int k = 0; k < BKK; k++) {
            float a[8], b[8];
            float4 t0 = *(const float4*)&As[k][ty * 8];
            float4 t1 = *(const float4*)&As[k][ty * 8 + 4];
            a[0] = t0.x; a[1] = t0.y; a[2] = t0.z; a[3] = t0.w;
            a[4] = t1.x; a[5] = t1.y; a[6] = t1.z; a[7] = t1.w;
            float4 u0 = *(const float4*)&Bs[k][tx * 8];
            float4 u1 = *(const float4*)&Bs[k][tx * 8 + 4];
            b[0] = u0.x; b[1] = u0.y; b[2] = u0.z; b[3] = u0.w;
            b[4] = u1.x; b[5] = u1.y; b[6] = u1.z; b[7] = u1.w;
#pragma unroll
            for (int i = 0; i < 8; i++)
#pragma unroll
                for (int jj = 0; jj < 8; jj++)
                    acc[i][jj] += a[i] * b[jj];
        }
        __syncthreads();
    }

#pragma unroll
    for (int ii = 0; ii < 8; ii++) {
        int m = m0 + ty * 8 + ii;
        int bb = m >> 11, l = m & 2047;
#pragma unroll
        for (int jj = 0; jj < 8; jj++) {
            int col = wn0 + tx * 8 + jj;
            int hh = col >> 6, e = col & 63;
            dst[(((size_t)bb * NHEAD + hh) * LSEQ + l) * EDIM + e] = acc[ii][jj] + bi[col];
        }
    }
}

// ---------------- output projection GEMM ------------------------------------
__global__ __launch_bounds__(256) void gemm_out(
    const float* __restrict__ Wo, const float* __restrict__ bo,
    float* __restrict__ out)
{
    __shared__ float As[BKK][BM + 4];
    __shared__ float Bs[BKK][BN + 4];

    const int tid = threadIdx.x;
    const int m0 = blockIdx.y * BM;
    const int n0 = blockIdx.x * BN;      // 0..511
    const int ty = tid >> 4, tx = tid & 15;

    float acc[8][8];
#pragma unroll
    for (int i = 0; i < 8; i++)
#pragma unroll
        for (int jj = 0; jj < 8; jj++) acc[i][jj] = 0.f;

    int rowi[2], c4o[2];
#pragma unroll
    for (int ff = 0; ff < 2; ff++) {
        int f = tid + ff * 256;
        rowi[ff] = f >> 2;
        c4o[ff] = (f & 3) << 2;
    }

    float4 pa[2], pb[2];
#pragma unroll
    for (int ff = 0; ff < 2; ff++) {
        pa[ff] = *(const float4*)(g_VO + (size_t)(m0 + rowi[ff]) * DMODEL + c4o[ff]);
        pb[ff] = *(const float4*)(Wo + (size_t)(n0 + rowi[ff]) * DMODEL + c4o[ff]);
    }

    for (int kt = 0; kt < DMODEL; kt += BKK) {
#pragma unroll
        for (int ff = 0; ff < 2; ff++) {
            int c4 = c4o[ff], rw = rowi[ff];
            As[c4 + 0][rw] = pa[ff].x; As[c4 + 1][rw] = pa[ff].y;
            As[c4 + 2][rw] = pa[ff].z; As[c4 + 3][rw] = pa[ff].w;
            Bs[c4 + 0][rw] = pb[ff].x; Bs[c4 + 1][rw] = pb[ff].y;
            Bs[c4 + 2][rw] = pb[ff].z; Bs[c4 + 3][rw] = pb[ff].w;
        }
        __syncthreads();
        if (kt + BKK < DMODEL) {
#pragma unroll
            for (int ff = 0; ff < 2; ff++) {
                pa[ff] = *(const float4*)(g_VO + (size_t)(m0 + rowi[ff]) * DMODEL + kt + BKK + c4o[ff]);
                pb[ff] = *(const float4*)(Wo + (size_t)(n0 + rowi[ff]) * DMODEL + kt + BKK + c4o[ff]);
            }
        }
#pragma unroll
        for (int k = 0; k < BKK; k++) {
            float a[8], b[8];
            float4 t0 = *(const float4*)&As[k][ty * 8];
            float4 t1 = *(const float4*)&As[k][ty * 8 + 4];
            a[0] = t0.x; a[1] = t0.y; a[2] = t0.z; a[3] = t0.w;
            a[4] = t1.x; a[5] = t1.y; a[6] = t1.z; a[7] = t1.w;
            float4 u0 = *(const float4*)&Bs[k][tx * 8];
            float4 u1 = *(const float4*)&Bs[k][tx * 8 + 4];
            b[0] = u0.x; b[1] = u0.y; b[2] = u0.z; b[3] = u0.w;
            b[4] = u1.x; b[5] = u1.y; b[6] = u1.z; b[7] = u1.w;
#pragma unroll
            for (int i = 0; i < 8; i++)
#pragma unroll
                for (int jj = 0; jj < 8; jj++)
                    acc[i][jj] += a[i] * b[jj];
        }
        __syncthreads();
    }

#pragma unroll
    for (int ii = 0; ii < 8; ii++) {
        int m = m0 + ty * 8 + ii;
#pragma unroll
        for (int jj = 0; jj < 8; jj++) {
            int col = n0 + tx * 8 + jj;
            out[(size_t)m * DMODEL + col] = acc[ii][jj] + bo[col];
        }
    }
}

// ---------------- RoPE (interleaved, first 32 dims of each head) ------------
__global__ void rope_k()
{
    int idx = blockIdx.x * 256 + threadIdx.x;   // B*H*L*16 = 524288
    int j = idx & 15;
    int l = (idx >> 4) & (LSEQ - 1);
    int bh = idx >> 15;                          // 0..15
    // theta_j = 10000^{-j/16}; compute in double for phase accuracy at l~2047
    double theta = exp(-(double)j * (9.210340371976184 / 16.0));
    double phi = (double)l * theta;
    double sd, cd;
    sincos(phi, &sd, &cd);
    float c = (float)cd, s = (float)sd;
    size_t base = (((size_t)bh * LSEQ) + l) * EDIM + 2 * j;
    float q0 = g_Q[base], q1 = g_Q[base + 1];
    g_Q[base]     = c * q0 - s * q1;
    g_Q[base + 1] = c * q1 + s * q0;
    float k0 = g_K[base], k1 = g_K[base + 1];
    g_K[base]     = c * k0 - s * k1;
    g_K[base + 1] = c * k1 + s * k0;
}

// ---------------- attention: diagonal causal 64x64 blocks -------------------
// blockIdx.x = b*256 + h*32 + vb. vb<31 -> normalized output; vb==31 -> partial.
__global__ __launch_bounds__(256) void attn_diag(const float* __restrict__ bias_emb)
{
    __shared__ float Qs[64 * 65];
    __shared__ float KVs[64 * 65];

    const int bx = blockIdx.x;
    const int vb = bx & 31;
    const int h  = (bx >> 5) & 7;
    const int bb = bx >> 8;
    const int tid = threadIdx.x;
    const size_t base = (((size_t)bb * NHEAD + h) * LSEQ + vb * 64) * EDIM;

#pragma unroll
    for (int t = 0; t < 16; t++) {
        int idx = t * 256 + tid;
        int rr = idx >> 6, e = idx & 63;
        Qs[rr * 65 + e]  = g_Q[base + rr * 64 + e];
        KVs[rr * 65 + e] = g_K[base + rr * 64 + e];
    }
    __syncthreads();

    const int r = tid >> 2, j = tid & 3;
    const float biasv = 0.125f * bias_emb[NHEAD + h];  // same-var bias, pre-scaled

    float s[16];
#pragma unroll
    for (int i = 0; i < 16; i++) s[i] = 0.f;

    float qreg[8];
    for (int e0 = 0; e0 < 64; e0 += 8) {
#pragma unroll
        for (int t = 0; t < 8; t++) qreg[t] = Qs[r * 65 + e0 + t];
#pragma unroll
        for (int i = 0; i < 16; i++) {
            int c = j + (i << 2);
            float a = 0.f;
#pragma unroll
            for (int t = 0; t < 8; t++) a += qreg[t] * KVs[c * 65 + e0 + t];
            s[i] += a;
        }
    }

    float mmax = -1e30f;
#pragma unroll
    for (int i = 0; i < 16; i++) {
        int c = j + (i << 2);
        s[i] = (c <= r) ? (0.125f * s[i] + biasv) : -1e30f;
        mmax = fmaxf(mmax, s[i]);
    }
    mmax = fmaxf(mmax, __shfl_xor_sync(0xffffffffu, mmax, 1));
    mmax = fmaxf(mmax, __shfl_xor_sync(0xffffffffu, mmax, 2));

    float lsum = 0.f;
#pragma unroll
    for (int i = 0; i < 16; i++) {
        int c = j + (i << 2);
        float p = (c <= r) ? __expf(s[i] - mmax) : 0.f;
        s[i] = p;
        lsum += p;
    }
    lsum += __shfl_xor_sync(0xffffffffu, lsum, 1);
    lsum += __shfl_xor_sync(0xffffffffu, lsum, 2);

    __syncthreads();  // done reading Qs/KVs

    // write P into Qs; load V (stride 64) into KVs
#pragma unroll
    for (int i = 0; i < 16; i++) Qs[r * 65 + j + (i << 2)] = s[i];
#pragma unroll
    for (int t = 0; t < 16; t++) {
        int idx = t * 256 + tid;
        int rr = idx >> 6, e = idx & 63;
        KVs[rr * 64 + e] = g_V[base + rr * 64 + e];
    }
    __syncthreads();

    float4 o0 = {0,0,0,0}, o1 = {0,0,0,0}, o2 = {0,0,0,0}, o3 = {0,0,0,0};
#pragma unroll 8
    for (int c = 0; c < 64; c++) {
        float pv = Qs[r * 65 + c];
        const float4* vp = (const float4*)&KVs[c * 64 + j * 16];
        float4 v0 = vp[0], v1 = vp[1], v2 = vp[2], v3 = vp[3];
        o0.x += pv * v0.x; o0.y += pv * v0.y; o0.z += pv * v0.z; o0.w += pv * v0.w;
        o1.x += pv * v1.x; o1.y += pv * v1.y; o1.z += pv * v1.z; o1.w += pv * v1.w;
        o2.x += pv * v2.x; o2.y += pv * v2.y; o2.z += pv * v2.z; o2.w += pv * v2.w;
        o3.x += pv * v3.x; o3.y += pv * v3.y; o3.z += pv * v3.z; o3.w += pv * v3.w;
    }

    if (vb < 31) {
        float inv = 1.f / lsum;
        int l = vb * 64 + r;
        float* ob = &g_VO[((size_t)bb * LSEQ + l) * DMODEL + h * 64 + j * 16];
        float4* o4 = (float4*)ob;
        o0.x *= inv; o0.y *= inv; o0.z *= inv; o0.w *= inv;
        o1.x *= inv; o1.y *= inv; o1.z *= inv; o1.w *= inv;
        o2.x *= inv; o2.y *= inv; o2.z *= inv; o2.w *= inv;
        o3.x *= inv; o3.y *= inv; o3.z *= inv; o3.w *= inv;
        o4[0] = o0; o4[1] = o1; o4[2] = o2; o4[3] = o3;
    } else {
        size_t bh = (size_t)bb * NHEAD + h;
        float* pb = &g_part[((bh * 32 + 31) * 64 + r) * 64 + j * 16];
        float4* p4 = (float4*)pb;
        p4[0] = o0; p4[1] = o1; p4[2] = o2; p4[3] = o3;
        if (j == 0) {
            size_t mb = ((bh * 32 + 31) * 64 + r) * 2;
            g_ml[mb] = mmax; g_ml[mb + 1] = lsum;
        }
    }
}

// ---------------- attention: last-var rows x early key chunks (partials) ----
// blockIdx.x in [0, B*H*31): chunk = x%31; h = (x/31)%8; b = x/248.
__global__ __launch_bounds__(256) void attn_last(const float* __restrict__ bias_emb)
{
    __shared__ float Qs[64 * 65];
    __shared__ float KVs[64 * 65];

    const int bx = blockIdx.x;
    const int chunk = bx % 31;
    const int t2 = bx / 31;
    const int h = t2 & 7;
    const int bb = t2 >> 3;
    const int tid = threadIdx.x;

    const size_t qbase = (((size_t)bb * NHEAD + h) * LSEQ + (LSEQ - 64)) * EDIM;
    const size_t kbase = (((size_t)bb * NHEAD + h) * LSEQ + chunk * 64) * EDIM;

#pragma unroll
    for (int t = 0; t < 16; t++) {
        int idx = t * 256 + tid;
        int rr = idx >> 6, e = idx & 63;
        Qs[rr * 65 + e]  = g_Q[qbase + rr * 64 + e];
        KVs[rr * 65 + e] = g_K[kbase + rr * 64 + e];
    }
    __syncthreads();

    const int r = tid >> 2, j = tid & 3;
    const float biasv = 0.125f * bias_emb[h];  // different-var bias, pre-scaled

    float s[16];
#pragma unroll
    for (int i = 0; i < 16; i++) s[i] = 0.f;

    float qreg[8];
    for (int e0 = 0; e0 < 64; e0 += 8) {
#pragma unroll
        for (int t = 0; t < 8; t++) qreg[t] = Qs[r * 65 + e0 + t];
#pragma unroll
        for (int i = 0; i < 16; i++) {
            int c = j + (i << 2);
            float a = 0.f;
#pragma unroll
            for (int t = 0; t < 8; t++) a += qreg[t] * KVs[c * 65 + e0 + t];
            s[i] += a;
        }
    }

    float mmax = -1e30f;
#pragma unroll
    for (int i = 0; i < 16; i++) {
        s[i] = 0.125f * s[i] + biasv;
        mmax = fmaxf(mmax, s[i]);
    }
    mmax = fmaxf(mmax, __shfl_xor_sync(0xffffffffu, mmax, 1));
    mmax = fmaxf(mmax, __shfl_xor_sync(0xffffffffu, mmax, 2));

    float lsum = 0.f;
#pragma unroll
    for (int i = 0; i < 16; i++) {
        float p = __expf(s[i] - mmax);
        s[i] = p;
        lsum += p;
    }
    lsum += __shfl_xor_sync(0xffffffffu, lsum, 1);
    lsum += __shfl_xor_sync(0xffffffffu, lsum, 2);

    __syncthreads();

#pragma unroll
    for (int i = 0; i < 16; i++) Qs[r * 65 + j + (i << 2)] = s[i];
#pragma unroll
    for (int t = 0; t < 16; t++) {
        int idx = t * 256 + tid;
        int rr = idx >> 6, e = idx & 63;
        KVs[rr * 64 + e] = g_V[kbase + rr * 64 + e];
    }
    __syncthreads();

    float4 o0 = {0,0,0,0}, o1 = {0,0,0,0}, o2 = {0,0,0,0}, o3 = {0,0,0,0};
#pragma unroll 8
    for (int c = 0; c < 64; c++) {
        float pv = Qs[r * 65 + c];
        const float4* vp = (const float4*)&KVs[c * 64 + j * 16];
        float4 v0 = vp[0], v1 = vp[1], v2 = vp[2], v3 = vp[3];
        o0.x += pv * v0.x; o0.y += pv * v0.y; o0.z += pv * v0.z; o0.w += pv * v0.w;
        o1.x += pv * v1.x; o1.y += pv * v1.y; o1.z += pv * v1.z; o1.w += pv * v1.w;
        o2.x += pv * v2.x; o2.y += pv * v2.y; o2.z += pv * v2.z; o2.w += pv * v2.w;
        o3.x += pv * v3.x; o3.y += pv * v3.y; o3.z += pv * v3.z; o3.w += pv * v3.w;
    }

    size_t bh = (size_t)bb * NHEAD + h;
    float* pb = &g_part[((bh * 32 + chunk) * 64 + r) * 64 + j * 16];
    float4* p4 = (float4*)pb;
    p4[0] = o0; p4[1] = o1; p4[2] = o2; p4[3] = o3;
    if (j == 0) {
        size_t mb = ((bh * 32 + chunk) * 64 + r) * 2;
        g_ml[mb] = mmax; g_ml[mb + 1] = lsum;
    }
}

// ---------------- attention: merge partials for last 64 rows ----------------
__global__ __launch_bounds__(256) void attn_merge()
{
    const int bh = blockIdx.x;          // 0..15
    const int bb = bh >> 3, h = bh & 7;
    const int tid = threadIdx.x;
    const int r = tid >> 2, j = tid & 3;

    float mstar = -1e30f;
    for (int c = 0; c < 32; c++)
        mstar = fmaxf(mstar, g_ml[(((size_t)bh * 32 + c) * 64 + r) * 2]);

    float Lsum = 0.f;
    float4 o0 = {0,0,0,0}, o1 = {0,0,0,0}, o2 = {0,0,0,0}, o3 = {0,0,0,0};
    for (int c = 0; c < 32; c++) {
        size_t mb = (((size_t)bh * 32 + c) * 64 + r) * 2;
        float mi = g_ml[mb];
        float li = g_ml[mb + 1];
        float w = __expf(mi - mstar);
        Lsum += w * li;
        const float4* pp = (const float4*)&g_part[(((size_t)bh * 32 + c) * 64 + r) * 64 + j * 16];
        float4 a0 = pp[0], a1 = pp[1], a2 = pp[2], a3 = pp[3];
        o0.x += w * a0.x; o0.y += w * a0.y; o0.z += w * a0.z; o0.w += w * a0.w;
        o1.x += w * a1.x; o1.y += w * a1.y; o1.z += w * a1.z; o1.w += w * a1.w;
        o2.x += w * a2.x; o2.y += w * a2.y; o2.z += w * a2.z; o2.w += w * a2.w;
        o3.x += w * a3.x; o3.y += w * a3.y; o3.z += w * a3.z; o3.w += w * a3.w;
    }
    float inv = 1.f / Lsum;
    int l = LSEQ - 64 + r;
    float4* o4 = (float4*)&g_VO[((size_t)bb * LSEQ + l) * DMODEL + h * 64 + j * 16];
    o0.x *= inv; o0.y *= inv; o0.z *= inv; o0.w *= inv;
    o1.x *= inv; o1.y *= inv; o1.z *= inv; o1.w *= inv;
    o2.x *= inv; o2.y *= inv; o2.z *= inv; o2.w *= inv;
    o3.x *= inv; o3.y *= inv; o3.z *= inv; o3.w *= inv;
    o4[0] = o0; o4[1] = o1; o4[2] = o2; o4[3] = o3;
}

// ---------------- launch ----------------------------------------------------
extern "C" void kernel_launch(void* const* d_in, const int* in_sizes, int n_in,
                              void* d_out, int out_size)
{
    (void)in_sizes; (void)n_in; (void)out_size;
    const float* x   = (const float*)d_in[0];
    const float* Wq  = (const float*)d_in[1];
    const float* bq  = (const float*)d_in[2];
    const float* Wk  = (const float*)d_in[3];
    const float* bk  = (const float*)d_in[4];
    const float* Wv  = (const float*)d_in[5];
    const float* bv  = (const float*)d_in[6];
    const float* Wo  = (const float*)d_in[7];
    const float* bo  = (const float*)d_in[8];
    const float* be  = (const float*)d_in[9];
    float* out = (float*)d_out;

    dim3 g1(12, 32);                       // N=1536, M=4096
    gemm_qkv<<<g1, 256>>>(x, Wq, bq, Wk, bk, Wv, bv);
    rope_k<<<2048, 256>>>();               // B*H*L*16 pairs
    attn_diag<<<BSZ * NHEAD * 32, 256>>>(be);
    attn_last<<<BSZ * NHEAD * 31, 256>>>(be);
    attn_merge<<<BSZ * NHEAD, 256>>>();
    dim3 g2(4, 32);                        // N=512, M=4096
    gemm_out<<<g2, 256>>>(Wo, bo, out);
}

// round 4
// speedup vs baseline: 1.4056x; 1.4056x over previous
#include <cuda_runtime.h>
#include <math.h>

// Problem constants (fixed shapes for this benchmark)
#define BSZ 2
#define LSEQ 2048
#define DMODEL 512
#define NHEAD 8
#define EDIM 64
#define NTOK 64
#define NVAR 32

// ---------------- scratch (device globals; no allocation allowed) ----------
__device__ float g_Q[BSZ * NHEAD * LSEQ * EDIM];   // [b][h][l][e]
__device__ float g_K[BSZ * NHEAD * LSEQ * EDIM];
__device__ float g_V[BSZ * NHEAD * LSEQ * EDIM];
__device__ float g_VO[BSZ * LSEQ * DMODEL];        // attention out, (B*L, D)
__device__ float g_part[BSZ * NHEAD * 32 * 64 * 64]; // partial accumulators
__device__ float g_ml[BSZ * NHEAD * 32 * 64 * 2];    // (m, l) per partial row

// ---------------- fused QKV projection GEMM --------------------------------
#define BM 128
#define BN 128
#define BKK 16

__global__ __launch_bounds__(256) void gemm_qkv(
    const float* __restrict__ x,
    const float* __restrict__ Wq, const float* __restrict__ bq,
    const float* __restrict__ Wk, const float* __restrict__ bk,
    const float* __restrict__ Wv, const float* __restrict__ bv)
{
    __shared__ float As[BKK][BM + 4];
    __shared__ float Bs[BKK][BN + 4];

    const int tid = threadIdx.x;
    const int m0 = blockIdx.y * BM;
    const int n0 = blockIdx.x * BN;      // 0..1535
    const int which = n0 >> 9;           // 0:q 1:k 2:v
    const int wn0 = n0 & 511;

    const float* W  = (which == 0) ? Wq : (which == 1) ? Wk : Wv;
    const float* bi = (which == 0) ? bq : (which == 1) ? bk : bv;
    float* dst      = (which == 0) ? g_Q : (which == 1) ? g_K : g_V;

    const int ty = tid >> 4, tx = tid & 15;

    float acc[8][8];
#pragma unroll
    for (int i = 0; i < 8; i++)
#pragma unroll
        for (int jj = 0; jj < 8; jj++) acc[i][jj] = 0.f;

    int rowi[2], c4o[2];
#pragma unroll
    for (int ff = 0; ff < 2; ff++) {
        int f = tid + ff * 256;
        rowi[ff] = f >> 2;
        c4o[ff] = (f & 3) << 2;
    }

    float4 pa[2], pb[2];
#pragma unroll
    for (int ff = 0; ff < 2; ff++) {
        pa[ff] = *(const float4*)(x + (size_t)(m0 + rowi[ff]) * DMODEL + c4o[ff]);
        pb[ff] = *(const float4*)(W + (size_t)(wn0 + rowi[ff]) * DMODEL + c4o[ff]);
    }

    for (int kt = 0; kt < DMODEL; kt += BKK) {
#pragma unroll
        for (int ff = 0; ff < 2; ff++) {
            int c4 = c4o[ff], rw = rowi[ff];
            As[c4 + 0][rw] = pa[ff].x; As[c4 + 1][rw] = pa[ff].y;
            As[c4 + 2][rw] = pa[ff].z; As[c4 + 3][rw] = pa[ff].w;
            Bs[c4 + 0][rw] = pb[ff].x; Bs[c4 + 1][rw] = pb[ff].y;
            Bs[c4 + 2][rw] = pb[ff].z; Bs[c4 + 3][rw] = pb[ff].w;
        }
        __syncthreads();
        if (kt + BKK < DMODEL) {
#pragma unroll
            for (int ff = 0; ff < 2; ff++) {
                pa[ff] = *(const float4*)(x + (size_t)(m0 + rowi[ff]) * DMODEL + kt + BKK + c4o[ff]);
                pb[ff] = *(const float4*)(W + (size_t)(wn0 + rowi[ff]) * DMODEL + kt + BKK + c4o[ff]);
            }
        }
#pragma unroll
        for (int k = 0; k < BKK; k++) {
            float a[8], b[8];
            float4 t0 = *(const float4*)&As[k][ty * 8];
            float4 t1 = *(const float4*)&As[k][ty * 8 + 4];
            a[0] = t0.x; a[1] = t0.y; a[2] = t0.z; a[3] = t0.w;
            a[4] = t1.x; a[5] = t1.y; a[6] = t1.z; a[7] = t1.w;
            float4 u0 = *(const float4*)&Bs[k][tx * 8];
            float4 u1 = *(const float4*)&Bs[k][tx * 8 + 4];
            b[0] = u0.x; b[1] = u0.y; b[2] = u0.z; b[3] = u0.w;
            b[4] = u1.x; b[5] = u1.y; b[6] = u1.z; b[7] = u1.w;
#pragma unroll
            for (int i = 0; i < 8; i++)
#pragma unroll
                for (int jj = 0; jj < 8; jj++)
                    acc[i][jj] += a[i] * b[jj];
        }
        __syncthreads();
    }

#pragma unroll
    for (int ii = 0; ii < 8; ii++) {
        int m = m0 + ty * 8 + ii;
        int bb = m >> 11, l = m & 2047;
#pragma unroll
        for (int jj = 0; jj < 8; jj++) {
            int col = wn0 + tx * 8 + jj;
            int hh = col >> 6, e = col & 63;
            dst[(((size_t)bb * NHEAD + hh) * LSEQ + l) * EDIM + e] = acc[ii][jj] + bi[col];
        }
    }
}

// ---------------- output projection GEMM ------------------------------------
__global__ __launch_bounds__(256) void gemm_out(
    const float* __restrict__ Wo, const float* __restrict__ bo,
    float* __restrict__ out)
{
    __shared__ float As[BKK][BM + 4];
    __shared__ float Bs[BKK][BN + 4];

    const int tid = threadIdx.x;
    const int m0 = blockIdx.y * BM;
    const int n0 = blockIdx.x * BN;
    const int ty = tid >> 4, tx = tid & 15;

    float acc[8][8];
#pragma unroll
    for (int i = 0; i < 8; i++)
#pragma unroll
        for (int jj = 0; jj < 8; jj++) acc[i][jj] = 0.f;

    int rowi[2], c4o[2];
#pragma unroll
    for (int ff = 0; ff < 2; ff++) {
        int f = tid + ff * 256;
        rowi[ff] = f >> 2;
        c4o[ff] = (f & 3) << 2;
    }

    float4 pa[2], pb[2];
#pragma unroll
    for (int ff = 0; ff < 2; ff++) {
        pa[ff] = *(const float4*)(g_VO + (size_t)(m0 + rowi[ff]) * DMODEL + c4o[ff]);
        pb[ff] = *(const float4*)(Wo + (size_t)(n0 + rowi[ff]) * DMODEL + c4o[ff]);
    }

    for (int kt = 0; kt < DMODEL; kt += BKK) {
#pragma unroll
        for (int ff = 0; ff < 2; ff++) {
            int c4 = c4o[ff], rw = rowi[ff];
            As[c4 + 0][rw] = pa[ff].x; As[c4 + 1][rw] = pa[ff].y;
            As[c4 + 2][rw] = pa[ff].z; As[c4 + 3][rw] = pa[ff].w;
            Bs[c4 + 0][rw] = pb[ff].x; Bs[c4 + 1][rw] = pb[ff].y;
            Bs[c4 + 2][rw] = pb[ff].z; Bs[c4 + 3][rw] = pb[ff].w;
        }
        __syncthreads();
        if (kt + BKK < DMODEL) {
#pragma unroll
            for (int ff = 0; ff < 2; ff++) {
                pa[ff] = *(const float4*)(g_VO + (size_t)(m0 + rowi[ff]) * DMODEL + kt + BKK + c4o[ff]);
                pb[ff] = *(const float4*)(Wo + (size_t)(n0 + rowi[ff]) * DMODEL + kt + BKK + c4o[ff]);
            }
        }
#pragma unroll
        for (int k = 0; k < BKK; k++) {
            float a[8], b[8];
            float4 t0 = *(const float4*)&As[k][ty * 8];
            float4 t1 = *(const float4*)&As[k][ty * 8 + 4];
            a[0] = t0.x; a[1] = t0.y; a[2] = t0.z; a[3] = t0.w;
            a[4] = t1.x; a[5] = t1.y; a[6] = t1.z; a[7] = t1.w;
            float4 u0 = *(const float4*)&Bs[k][tx * 8];
            float4 u1 = *(const float4*)&Bs[k][tx * 8 + 4];
            b[0] = u0.x; b[1] = u0.y; b[2] = u0.z; b[3] = u0.w;
            b[4] = u1.x; b[5] = u1.y; b[6] = u1.z; b[7] = u1.w;
#pragma unroll
            for (int i = 0; i < 8; i++)
#pragma unroll
                for (int jj = 0; jj < 8; jj++)
                    acc[i][jj] += a[i] * b[jj];
        }
        __syncthreads();
    }

#pragma unroll
    for (int ii = 0; ii < 8; ii++) {
        int m = m0 + ty * 8 + ii;
#pragma unroll
        for (int jj = 0; jj < 8; jj++) {
            int col = n0 + tx * 8 + jj;
            out[(size_t)m * DMODEL + col] = acc[ii][jj] + bo[col];
        }
    }
}

// ---------------- RoPE (interleaved, first 32 dims of each head), fp32 ------
__global__ void rope_k()
{
    int idx = blockIdx.x * 256 + threadIdx.x;   // B*H*L*16 = 524288
    int j = idx & 15;
    int l = (idx >> 4) & (LSEQ - 1);
    int bh = idx >> 15;                          // 0..15
    // theta_j = 10000^{-j/16} = 2^{-j*log2(10000)/16}
    float theta = exp2f(-(float)j * 0.83048202372184f);
    float phi = (float)l * theta;
    float sv, cv;
    sincosf(phi, &sv, &cv);
    size_t base = (((size_t)bh * LSEQ) + l) * EDIM + 2 * j;
    float q0 = g_Q[base], q1 = g_Q[base + 1];
    g_Q[base]     = cv * q0 - sv * q1;
    g_Q[base + 1] = cv * q1 + sv * q0;
    float k0 = g_K[base], k1 = g_K[base + 1];
    g_K[base]     = cv * k0 - sv * k1;
    g_K[base + 1] = cv * k1 + sv * k0;
}

// ---------------- attention: merged diag + last-rows kernel -----------------
// bx < 512: diagonal causal 64x64 block (vb = bx&31). vb<31 -> normalized out,
//           vb==31 -> partial slot 31.
// bx >= 512: last-64-rows x early chunk (partial slots 0..30).
#define STR 68   // smem row stride (floats): 16B-aligned, conflict-managed

__global__ __launch_bounds__(256) void attn_main(const float* __restrict__ be)
{
    __shared__ float Ash[64 * STR];   // phase1: Q^T [e][row]; phase2: P^T [c][row]
    __shared__ float Bsh[64 * STR];   // phase1: K^T [e][col]; phase2: V [c][e]

    const int bx = blockIdx.x;
    const int tid = threadIdx.x;

    int bb, h, qrow0, krow0, slot;
    bool diag;
    if (bx < 512) {
        int vb = bx & 31; h = (bx >> 5) & 7; bb = bx >> 8;
        qrow0 = vb * 64; krow0 = vb * 64; slot = vb; diag = true;
    } else {
        int y = bx - 512;
        int chunk = y % 31; int t2 = y / 31; h = t2 & 7; bb = t2 >> 3;
        qrow0 = LSEQ - 64; krow0 = chunk * 64; slot = chunk; diag = false;
    }
    const size_t bhbase = ((size_t)bb * NHEAD + h) * LSEQ;
    const float* Qg = g_Q + (bhbase + qrow0) * EDIM;
    const float* Kg = g_K + (bhbase + krow0) * EDIM;
    const float* Vg = g_V + (bhbase + krow0) * EDIM;

    // ---- stage Q^T and K^T (transpose during store) ----
#pragma unroll
    for (int t = 0; t < 4; t++) {
        int idx = t * 256 + tid;
        int row = idx >> 4;
        int e0 = (idx & 15) << 2;
        float4 q = *(const float4*)(Qg + row * 64 + e0);
        float4 k = *(const float4*)(Kg + row * 64 + e0);
        Ash[(e0 + 0) * STR + row] = q.x; Ash[(e0 + 1) * STR + row] = q.y;
        Ash[(e0 + 2) * STR + row] = q.z; Ash[(e0 + 3) * STR + row] = q.w;
        Bsh[(e0 + 0) * STR + row] = k.x; Bsh[(e0 + 1) * STR + row] = k.y;
        Bsh[(e0 + 2) * STR + row] = k.z; Bsh[(e0 + 3) * STR + row] = k.w;
    }
    __syncthreads();

    const int ty = tid >> 4, tx = tid & 15;
    const int r0 = ty << 2, c0 = tx << 2;
    const float biasv = 0.125f * (diag ? be[NHEAD + h] : be[h]);

    // ---- S = Q K^T : 4x4 register tile, a-frag broadcast, b-frag conflict-free
    float s[4][4];
#pragma unroll
    for (int i = 0; i < 4; i++)
#pragma unroll
        for (int j = 0; j < 4; j++) s[i][j] = 0.f;

#pragma unroll 8
    for (int e = 0; e < 64; e++) {
        float4 a4 = *(const float4*)&Ash[e * STR + r0];
        float4 b4 = *(const float4*)&Bsh[e * STR + c0];
        float a[4] = {a4.x, a4.y, a4.z, a4.w};
        float b[4] = {b4.x, b4.y, b4.z, b4.w};
#pragma unroll
        for (int i = 0; i < 4; i++)
#pragma unroll
            for (int j = 0; j < 4; j++)
                s[i][j] += a[i] * b[j];
    }

    // ---- mask + bias + row softmax stats (rows live in 16-lane tx groups) --
    float m[4], l[4];
#pragma unroll
    for (int i = 0; i < 4; i++) {
        float mm = -1e30f;
#pragma unroll
        for (int j = 0; j < 4; j++) {
            float v = 0.125f * s[i][j] + biasv;
            if (diag && (c0 + j > r0 + i)) v = -1e30f;
            s[i][j] = v;
            mm = fmaxf(mm, v);
        }
        mm = fmaxf(mm, __shfl_xor_sync(0xffffffffu, mm, 1));
        mm = fmaxf(mm, __shfl_xor_sync(0xffffffffu, mm, 2));
        mm = fmaxf(mm, __shfl_xor_sync(0xffffffffu, mm, 4));
        mm = fmaxf(mm, __shfl_xor_sync(0xffffffffu, mm, 8));
        m[i] = mm;
        float ls = 0.f;
#pragma unroll
        for (int j = 0; j < 4; j++) {
            float p = __expf(s[i][j] - mm);
            s[i][j] = p;
            ls += p;
        }
        ls += __shfl_xor_sync(0xffffffffu, ls, 1);
        ls += __shfl_xor_sync(0xffffffffu, ls, 2);
        ls += __shfl_xor_sync(0xffffffffu, ls, 4);
        ls += __shfl_xor_sync(0xffffffffu, ls, 8);
        l[i] = ls;
    }

    __syncthreads();   // all reads of phase-1 Ash/Bsh complete

    // ---- write P^T [c][row]; stage V [c][e] ----
#pragma unroll
    for (int i = 0; i < 4; i++)
#pragma unroll
        for (int j = 0; j < 4; j++)
            Ash[(c0 + j) * STR + r0 + i] = s[i][j];
#pragma unroll
    for (int t = 0; t < 4; t++) {
        int idx = t * 256 + tid;
        int c = idx >> 4;
        int e0 = (idx & 15) << 2;
        *(float4*)&Bsh[c * STR + e0] = *(const float4*)(Vg + c * 64 + e0);
    }
    __syncthreads();

    // ---- O = P V : 4 rows x 4 e-cols per thread ----
    float o[4][4];
#pragma unroll
    for (int i = 0; i < 4; i++)
#pragma unroll
        for (int j = 0; j < 4; j++) o[i][j] = 0.f;

#pragma unroll 8
    for (int c = 0; c < 64; c++) {
        float4 a4 = *(const float4*)&Ash[c * STR + r0];
        float4 b4 = *(const float4*)&Bsh[c * STR + c0];
        float a[4] = {a4.x, a4.y, a4.z, a4.w};
        float b[4] = {b4.x, b4.y, b4.z, b4.w};
#pragma unroll
        for (int i = 0; i < 4; i++)
#pragma unroll
            for (int j = 0; j < 4; j++)
                o[i][j] += a[i] * b[j];
    }

    // ---- epilogue ----
    if (diag && slot < 31) {
#pragma unroll
        for (int i = 0; i < 4; i++) {
            float inv = 1.f / l[i];
            int ll = qrow0 + r0 + i;
            float4 w;
            w.x = o[i][0] * inv; w.y = o[i][1] * inv;
            w.z = o[i][2] * inv; w.w = o[i][3] * inv;
            *(float4*)&g_VO[((size_t)bb * LSEQ + ll) * DMODEL + h * 64 + c0] = w;
        }
    } else {
        size_t bh = (size_t)bb * NHEAD + h;
#pragma unroll
        for (int i = 0; i < 4; i++) {
            float4 w;
            w.x = o[i][0]; w.y = o[i][1]; w.z = o[i][2]; w.w = o[i][3];
            *(float4*)&g_part[(((bh * 32 + slot) * 64) + r0 + i) * 64 + c0] = w;
            if (tx == 0) {
                size_t mb = (((bh * 32 + slot) * 64) + r0 + i) * 2;
                g_ml[mb] = m[i]; g_ml[mb + 1] = l[i];
            }
        }
    }
}

// ---------------- attention: merge partials for last 64 rows ----------------
__global__ __launch_bounds__(256) void attn_merge()
{
    const int bh = blockIdx.x;          // 0..15
    const int bb = bh >> 3, h = bh & 7;
    const int tid = threadIdx.x;
    const int r = tid >> 2, j = tid & 3;

    float mstar = -1e30f;
    for (int c = 0; c < 32; c++)
        mstar = fmaxf(mstar, g_ml[(((size_t)bh * 32 + c) * 64 + r) * 2]);

    float Lsum = 0.f;
    float4 o0 = {0,0,0,0}, o1 = {0,0,0,0}, o2 = {0,0,0,0}, o3 = {0,0,0,0};
    for (int c = 0; c < 32; c++) {
        size_t mb = (((size_t)bh * 32 + c) * 64 + r) * 2;
        float mi = g_ml[mb];
        float li = g_ml[mb + 1];
        float w = __expf(mi - mstar);
        Lsum += w * li;
        const float4* pp = (const float4*)&g_part[(((size_t)bh * 32 + c) * 64 + r) * 64 + j * 16];
        float4 a0 = pp[0], a1 = pp[1], a2 = pp[2], a3 = pp[3];
        o0.x += w * a0.x; o0.y += w * a0.y; o0.z += w * a0.z; o0.w += w * a0.w;
        o1.x += w * a1.x; o1.y += w * a1.y; o1.z += w * a1.z; o1.w += w * a1.w;
        o2.x += w * a2.x; o2.y += w * a2.y; o2.z += w * a2.z; o2.w += w * a2.w;
        o3.x += w * a3.x; o3.y += w * a3.y; o3.z += w * a3.z; o3.w += w * a3.w;
    }
    float inv = 1.f / Lsum;
    int l = LSEQ - 64 + r;
    float4* o4 = (float4*)&g_VO[((size_t)bb * LSEQ + l) * DMODEL + h * 64 + j * 16];
    o0.x *= inv; o0.y *= inv; o0.z *= inv; o0.w *= inv;
    o1.x *= inv; o1.y *= inv; o1.z *= inv; o1.w *= inv;
    o2.x *= inv; o2.y *= inv; o2.z *= inv; o2.w *= inv;
    o3.x *= inv; o3.y *= inv; o3.z *= inv; o3.w *= inv;
    o4[0] = o0; o4[1] = o1; o4[2] = o2; o4[3] = o3;
}

// ---------------- launch ----------------------------------------------------
extern "C" void kernel_launch(void* const* d_in, const int* in_sizes, int n_in,
                              void* d_out, int out_size)
{
    (void)in_sizes; (void)n_in; (void)out_size;
    const float* x   = (const float*)d_in[0];
    const float* Wq  = (const float*)d_in[1];
    const float* bq  = (const float*)d_in[2];
    const float* Wk  = (const float*)d_in[3];
    const float* bk  = (const float*)d_in[4];
    const float* Wv  = (const float*)d_in[5];
    const float* bv  = (const float*)d_in[6];
    const float* Wo  = (const float*)d_in[7];
    const float* bo  = (const float*)d_in[8];
    const float* be  = (const float*)d_in[9];
    float* out = (float*)d_out;

    dim3 g1(12, 32);                       // N=1536, M=4096
    gemm_qkv<<<g1, 256>>>(x, Wq, bq, Wk, bk, Wv, bv);
    rope_k<<<2048, 256>>>();               // B*H*L*16 pairs
    attn_main<<<512 + BSZ * NHEAD * 31, 256>>>(be);
    attn_merge<<<BSZ * NHEAD, 256>>>();
    dim3 g2(4, 32);                        // N=512, M=4096
    gemm_out<<<g2, 256>>>(Wo, bo, out);
}

// round 8
// speedup vs baseline: 1.9014x; 1.3528x over previous
#include <cuda_runtime.h>
#include <cuda_bf16.h>
#include <math.h>
#include <stdint.h>

// Problem constants (fixed shapes for this benchmark)
#define BSZ 2
#define LSEQ 2048
#define DMODEL 512
#define NHEAD 8
#define EDIM 64
#define NTOK 64
#define NVAR 32

// ---------------- scratch (device globals; no allocation allowed) ----------
__device__ float g_Q[BSZ * NHEAD * LSEQ * EDIM];   // [b][h][l][e]
__device__ float g_K[BSZ * NHEAD * LSEQ * EDIM];
__device__ float g_V[BSZ * NHEAD * LSEQ * EDIM];
__device__ float g_VO[BSZ * LSEQ * DMODEL];        // attention out, (B*L, D)
__device__ float g_part[BSZ * NHEAD * 32 * 64 * 64]; // partial accumulators
__device__ float g_ml[BSZ * NHEAD * 32 * 64 * 2];    // (m, l) per partial row

__device__ __forceinline__ uint32_t smem_u32(const void* p) {
    uint32_t a;
    asm("{ .reg .u64 t; cvta.to.shared.u64 t, %1; cvt.u32.u64 %0, t; }"
        : "=r"(a) : "l"(p));
    return a;
}

// SW128 swizzle at byte granularity (128B rows)
#define SWZ128(o) ((o) ^ (((o) >> 3) & 0x70))

// ============ bf16 hi/lo split GEMM via mma.sync (sm_80 PTX path) ===========
// C[m,n] = sum_k A[m,k]*W[n,k] + bias[n] computed as Ah*Bh + Ah*Bl + Al*Bh.
// Logical K' = 3*512 = 1536, chunked by 64. MODE 0: QKV scatter; 1: out proj.
#define GBM 128
#define GBN 128
#define GBK 64

// Convert float4 -> 4 bf16 (hi or lo part), store 8B at swizzled (row, c4*2)
__device__ __forceinline__ void stage_bf16x4(
    uint8_t* smem, int row, int c4, float4 v, bool lo)
{
    __nv_bfloat16 h0 = __float2bfloat16(v.x);
    __nv_bfloat16 h1 = __float2bfloat16(v.y);
    __nv_bfloat16 h2 = __float2bfloat16(v.z);
    __nv_bfloat16 h3 = __float2bfloat16(v.w);
    if (lo) {
        h0 = __float2bfloat16(v.x - __bfloat162float(h0));
        h1 = __float2bfloat16(v.y - __bfloat162float(h1));
        h2 = __float2bfloat16(v.z - __bfloat162float(h2));
        h3 = __float2bfloat16(v.w - __bfloat162float(h3));
    }
    uint2 p;
    p.x = (uint32_t)__bfloat16_as_ushort(h0) | ((uint32_t)__bfloat16_as_ushort(h1) << 16);
    p.y = (uint32_t)__bfloat16_as_ushort(h2) | ((uint32_t)__bfloat16_as_ushort(h3) << 16);
    uint32_t off = SWZ128((uint32_t)(row * 128 + c4 * 2));
    *(uint2*)(smem + off) = p;
}

__device__ __forceinline__ void ldm_x4(uint32_t r[4], uint32_t addr)
{
    asm volatile("ldmatrix.sync.aligned.m8n8.x4.shared.b16 {%0,%1,%2,%3}, [%4];"
                 : "=r"(r[0]), "=r"(r[1]), "=r"(r[2]), "=r"(r[3]) : "r"(addr));
}

__device__ __forceinline__ void mma_16816(
    float c[4], uint32_t a0, uint32_t a1, uint32_t a2, uint32_t a3,
    uint32_t b0, uint32_t b1)
{
    asm volatile(
        "mma.sync.aligned.m16n8k16.row.col.f32.bf16.bf16.f32 "
        "{%0,%1,%2,%3}, {%4,%5,%6,%7}, {%8,%9}, {%0,%1,%2,%3};"
        : "+f"(c[0]), "+f"(c[1]), "+f"(c[2]), "+f"(c[3])
        : "r"(a0), "r"(a1), "r"(a2), "r"(a3), "r"(b0), "r"(b1));
}

template <int MODE>
__global__ __launch_bounds__(256) void gemm_mma(
    const float* __restrict__ A,
    const float* __restrict__ W0, const float* __restrict__ W1, const float* __restrict__ W2,
    const float* __restrict__ b0v, const float* __restrict__ b1v, const float* __restrict__ b2v,
    float* __restrict__ outp)
{
    __shared__ __align__(16) uint8_t Asm[GBM * GBK * 2];   // 16 KB bf16, SW128
    __shared__ __align__(16) uint8_t Bsm[GBN * GBK * 2];   // 16 KB

    const int tid = threadIdx.x;
    const int lane = tid & 31;
    const int warp = tid >> 5;
    const int warp_m = warp >> 2;        // 0..1  (64-row slab)
    const int warp_n = warp & 3;         // 0..3  (32-col slab)

    const int nt = blockIdx.x, mt = blockIdx.y;
    const int m0 = mt * GBM;
    const int which = (MODE == 0) ? (nt >> 2) : 0;
    const float* W    = (MODE == 0) ? ((which == 0) ? W0 : (which == 1) ? W1 : W2) : W0;
    const float* bias = (MODE == 0) ? ((which == 0) ? b0v : (which == 1) ? b1v : b2v) : b0v;
    const int wn0 = (MODE == 0) ? ((nt & 3) * GBN) : nt * GBN;
    const float* Asrc = (MODE == 0) ? A : g_VO;

    const uint32_t asm_b = smem_u32(Asm);
    const uint32_t bsm_b = smem_u32(Bsm);

    float C[4][4][4];
#pragma unroll
    for (int i = 0; i < 4; i++)
#pragma unroll
        for (int j = 0; j < 4; j++)
#pragma unroll
            for (int q = 0; q < 4; q++) C[i][j][q] = 0.f;

    // precomputed staging coordinates: idx = it*256+tid; row = idx>>4 (16 rows/step)
    const int srow = tid >> 4;           // base row within 16-row group
    const int sc4  = (tid & 15) << 2;    // float4 col offset (0..60)

    for (int cc = 0; cc < 24; cc++) {
        const int pass = cc >> 3;
        const int k0 = (cc & 7) << 6;
        const bool aLo = (pass == 1);
        const bool bLo = (pass == 2);

        // ---- stage A and B chunk (fp32 -> bf16 hi/lo), SW128 swizzled ----
#pragma unroll
        for (int it = 0; it < 8; it++) {
            int row = it * 16 + srow;
            float4 va = *(const float4*)(Asrc + (size_t)(m0 + row) * DMODEL + k0 + sc4);
            stage_bf16x4(Asm, row, sc4, va, aLo);
            float4 vb = *(const float4*)(W + (size_t)(wn0 + row) * DMODEL + k0 + sc4);
            stage_bf16x4(Bsm, row, sc4, vb, bLo);
        }
        __syncthreads();

        // ---- compute: 4 k16 steps ----
#pragma unroll
        for (int ks = 0; ks < 4; ks++) {
            const int kb = (ks * 16 + (lane >> 4) * 8) * 2;   // byte col for ldmatrix
            uint32_t a[4][4];
#pragma unroll
            for (int mf = 0; mf < 4; mf++) {
                int row = warp_m * 64 + mf * 16 + (lane & 15);
                ldm_x4(a[mf], asm_b + SWZ128((uint32_t)(row * 128 + kb)));
            }
            uint32_t br[2][4];
#pragma unroll
            for (int np = 0; np < 2; np++) {
                int row = warp_n * 32 + np * 16 + (lane & 15);
                ldm_x4(br[np], bsm_b + SWZ128((uint32_t)(row * 128 + kb)));
            }
            // b frags: nblock (np*2+0) = {r0, r2}; (np*2+1) = {r1, r3}
#pragma unroll
            for (int mf = 0; mf < 4; mf++) {
#pragma unroll
                for (int np = 0; np < 2; np++) {
                    mma_16816(C[mf][np * 2 + 0], a[mf][0], a[mf][1], a[mf][2], a[mf][3],
                              br[np][0], br[np][2]);
                    mma_16816(C[mf][np * 2 + 1], a[mf][0], a[mf][1], a[mf][2], a[mf][3],
                              br[np][1], br[np][3]);
                }
            }
        }
        __syncthreads();
    }

    // ---- epilogue: bias add + store ----
    float* dst = (MODE == 0) ? ((which == 0) ? g_Q : (which == 1) ? g_K : g_V) : outp;
#pragma unroll
    for (int mf = 0; mf < 4; mf++) {
#pragma unroll
        for (int nf = 0; nf < 4; nf++) {
            int colg = wn0 + warp_n * 32 + nf * 8 + (lane & 3) * 2;
            float bx = bias[colg], by = bias[colg + 1];
#pragma unroll
            for (int half = 0; half < 2; half++) {
                int m = m0 + warp_m * 64 + mf * 16 + (lane >> 2) + half * 8;
                float2 o;
                o.x = C[mf][nf][half * 2 + 0] + bx;
                o.y = C[mf][nf][half * 2 + 1] + by;
                if (MODE == 0) {
                    int bb = m >> 11, l = m & 2047;
                    int hh = colg >> 6, e = colg & 63;
                    *(float2*)&dst[(((size_t)bb * NHEAD + hh) * LSEQ + l) * EDIM + e] = o;
                } else {
                    *(float2*)&dst[(size_t)m * DMODEL + colg] = o;
                }
            }
        }
    }
}

// ---------------- RoPE (interleaved, first 32 dims of each head), fp32 ------
__global__ void rope_k()
{
    int idx = blockIdx.x * 256 + threadIdx.x;   // B*H*L*16 = 524288
    int j = idx & 15;
    int l = (idx >> 4) & (LSEQ - 1);
    int bh = idx >> 15;                          // 0..15
    float theta = exp2f(-(float)j * 0.83048202372184f);  // 10000^{-j/16}
    float phi = (float)l * theta;
    float sv, cv;
    sincosf(phi, &sv, &cv);
    size_t base = (((size_t)bh * LSEQ) + l) * EDIM + 2 * j;
    float q0 = g_Q[base], q1 = g_Q[base + 1];
    g_Q[base]     = cv * q0 - sv * q1;
    g_Q[base + 1] = cv * q1 + sv * q0;
    float k0 = g_K[base], k1 = g_K[base + 1];
    g_K[base]     = cv * k0 - sv * k1;
    g_K[base + 1] = cv * k1 + sv * k0;
}

// ---------------- attention: merged diag + last-rows kernel -----------------
#define STR 68   // smem row stride (floats)

__global__ __launch_bounds__(256) void attn_main(const float* __restrict__ be)
{
    __shared__ float Ash[64 * STR];   // phase1: Q^T [e][row]; phase2: P^T [c][row]
    __shared__ float Bsh[64 * STR];   // phase1: K^T [e][col]; phase2: V [c][e]

    const int bx = blockIdx.x;
    const int tid = threadIdx.x;

    int bb, h, qrow0, krow0, slot;
    bool diag;
    if (bx < 512) {
        int vb = bx & 31; h = (bx >> 5) & 7; bb = bx >> 8;
        qrow0 = vb * 64; krow0 = vb * 64; slot = vb; diag = true;
    } else {
        int y = bx - 512;
        int chunk = y % 31; int t2 = y / 31; h = t2 & 7; bb = t2 >> 3;
        qrow0 = LSEQ - 64; krow0 = chunk * 64; slot = chunk; diag = false;
    }
    const size_t bhbase = ((size_t)bb * NHEAD + h) * LSEQ;
    const float* Qg = g_Q + (bhbase + qrow0) * EDIM;
    const float* Kg = g_K + (bhbase + krow0) * EDIM;
    const float* Vg = g_V + (bhbase + krow0) * EDIM;

#pragma unroll
    for (int t = 0; t < 4; t++) {
        int idx = t * 256 + tid;
        int row = idx >> 4;
        int e0 = (idx & 15) << 2;
        float4 q = *(const float4*)(Qg + row * 64 + e0);
        float4 k = *(const float4*)(Kg + row * 64 + e0);
        Ash[(e0 + 0) * STR + row] = q.x; Ash[(e0 + 1) * STR + row] = q.y;
        Ash[(e0 + 2) * STR + row] = q.z; Ash[(e0 + 3) * STR + row] = q.w;
        Bsh[(e0 + 0) * STR + row] = k.x; Bsh[(e0 + 1) * STR + row] = k.y;
        Bsh[(e0 + 2) * STR + row] = k.z; Bsh[(e0 + 3) * STR + row] = k.w;
    }
    __syncthreads();

    const int ty = tid >> 4, tx = tid & 15;
    const int r0 = ty << 2, c0 = tx << 2;
    const float biasv = 0.125f * (diag ? be[NHEAD + h] : be[h]);

    float s[4][4];
#pragma unroll
    for (int i = 0; i < 4; i++)
#pragma unroll
        for (int j = 0; j < 4; j++) s[i][j] = 0.f;

#pragma unroll 8
    for (int e = 0; e < 64; e++) {
        float4 a4 = *(const float4*)&Ash[e * STR + r0];
        float4 b4 = *(const float4*)&Bsh[e * STR + c0];
        float a[4] = {a4.x, a4.y, a4.z, a4.w};
        float b[4] = {b4.x, b4.y, b4.z, b4.w};
#pragma unroll
        for (int i = 0; i < 4; i++)
#pragma unroll
            for (int j = 0; j < 4; j++)
                s[i][j] += a[i] * b[j];
    }

    float m[4], l[4];
#pragma unroll
    for (int i = 0; i < 4; i++) {
        float mm = -1e30f;
#pragma unroll
        for (int j = 0; j < 4; j++) {
            float v = 0.125f * s[i][j] + biasv;
            if (diag && (c0 + j > r0 + i)) v = -1e30f;
            s[i][j] = v;
            mm = fmaxf(mm, v);
        }
        mm = fmaxf(mm, __shfl_xor_sync(0xffffffffu, mm, 1));
        mm = fmaxf(mm, __shfl_xor_sync(0xffffffffu, mm, 2));
        mm = fmaxf(mm, __shfl_xor_sync(0xffffffffu, mm, 4));
        mm = fmaxf(mm, __shfl_xor_sync(0xffffffffu, mm, 8));
        m[i] = mm;
        float ls = 0.f;
#pragma unroll
        for (int j = 0; j < 4; j++) {
            float p = __expf(s[i][j] - mm);
            s[i][j] = p;
            ls += p;
        }
        ls += __shfl_xor_sync(0xffffffffu, ls, 1);
        ls += __shfl_xor_sync(0xffffffffu, ls, 2);
        ls += __shfl_xor_sync(0xffffffffu, ls, 4);
        ls += __shfl_xor_sync(0xffffffffu, ls, 8);
        l[i] = ls;
    }

    __syncthreads();

#pragma unroll
    for (int i = 0; i < 4; i++)
#pragma unroll
        for (int j = 0; j < 4; j++)
            Ash[(c0 + j) * STR + r0 + i] = s[i][j];
#pragma unroll
    for (int t = 0; t < 4; t++) {
        int idx = t * 256 + tid;
        int c = idx >> 4;
        int e0 = (idx & 15) << 2;
        *(float4*)&Bsh[c * STR + e0] = *(const float4*)(Vg + c * 64 + e0);
    }
    __syncthreads();

    float o[4][4];
#pragma unroll
    for (int i = 0; i < 4; i++)
#pragma unroll
        for (int j = 0; j < 4; j++) o[i][j] = 0.f;

#pragma unroll 8
    for (int c = 0; c < 64; c++) {
        float4 a4 = *(const float4*)&Ash[c * STR + r0];
        float4 b4 = *(const float4*)&Bsh[c * STR + c0];
        float a[4] = {a4.x, a4.y, a4.z, a4.w};
        float b[4] = {b4.x, b4.y, b4.z, b4.w};
#pragma unroll
        for (int i = 0; i < 4; i++)
#pragma unroll
            for (int j = 0; j < 4; j++)
                o[i][j] += a[i] * b[j];
    }

    if (diag && slot < 31) {
#pragma unroll
        for (int i = 0; i < 4; i++) {
            float inv = 1.f / l[i];
            int ll = qrow0 + r0 + i;
            float4 w;
            w.x = o[i][0] * inv; w.y = o[i][1] * inv;
            w.z = o[i][2] * inv; w.w = o[i][3] * inv;
            *(float4*)&g_VO[((size_t)bb * LSEQ + ll) * DMODEL + h * 64 + c0] = w;
        }
    } else {
        size_t bh = (size_t)bb * NHEAD + h;
#pragma unroll
        for (int i = 0; i < 4; i++) {
            float4 w;
            w.x = o[i][0]; w.y = o[i][1]; w.z = o[i][2]; w.w = o[i][3];
            *(float4*)&g_part[(((bh * 32 + slot) * 64) + r0 + i) * 64 + c0] = w;
            if (tx == 0) {
                size_t mb = (((bh * 32 + slot) * 64) + r0 + i) * 2;
                g_ml[mb] = m[i]; g_ml[mb + 1] = l[i];
            }
        }
    }
}

// ---------------- attention: merge partials (256 CTAs, 4 rows each) --------
__global__ __launch_bounds__(256) void attn_merge()
{
    __shared__ float sw[4][32];
    __shared__ float sinv[4];

    const int bx = blockIdx.x;          // 0..255
    const int bh = bx >> 4;
    const int r0 = (bx & 15) << 2;
    const int tid = threadIdx.x;

    if (tid < 128) {
        int i = tid >> 5, c = tid & 31;
        size_t mb = (((size_t)bh * 32 + c) * 64 + r0 + i) * 2;
        float mi = g_ml[mb];
        float li = g_ml[mb + 1];
        float mv = mi;
#pragma unroll
        for (int o = 16; o; o >>= 1) mv = fmaxf(mv, __shfl_xor_sync(0xffffffffu, mv, o));
        float w = __expf(mi - mv);
        float lw = w * li;
#pragma unroll
        for (int o = 16; o; o >>= 1) lw += __shfl_xor_sync(0xffffffffu, lw, o);
        sw[i][c] = w;
        if (c == 0) sinv[i] = 1.f / lw;
    }
    __syncthreads();

    const int i = tid >> 6, e = tid & 63;
    const int r = r0 + i;
    const float* pbase = &g_part[(((size_t)bh * 32) * 64 + r) * 64 + e];
    float acc = 0.f;
#pragma unroll 4
    for (int c = 0; c < 32; c++)
        acc += sw[i][c] * pbase[(size_t)c * 64 * 64];

    const int bb = bh >> 3, h = bh & 7;
    g_VO[((size_t)bb * LSEQ + (LSEQ - 64 + r)) * DMODEL + h * 64 + e] = acc * sinv[i];
}

// ---------------- launch ----------------------------------------------------
extern "C" void kernel_launch(void* const* d_in, const int* in_sizes, int n_in,
                              void* d_out, int out_size)
{
    (void)in_sizes; (void)n_in; (void)out_size;
    const float* x   = (const float*)d_in[0];
    const float* Wq  = (const float*)d_in[1];
    const float* bq  = (const float*)d_in[2];
    const float* Wk  = (const float*)d_in[3];
    const float* bk  = (const float*)d_in[4];
    const float* Wv  = (const float*)d_in[5];
    const float* bv  = (const float*)d_in[6];
    const float* Wo  = (const float*)d_in[7];
    const float* bo  = (const float*)d_in[8];
    const float* be  = (const float*)d_in[9];
    float* out = (float*)d_out;

    dim3 g1(12, 32);                       // N=1536 (3 x 512), M=4096
    gemm_mma<0><<<g1, 256>>>(x, Wq, Wk, Wv, bq, bk, bv, nullptr);
    rope_k<<<2048, 256>>>();               // B*H*L*16 pairs
    attn_main<<<512 + BSZ * NHEAD * 31, 256>>>(be);
    attn_merge<<<256, 256>>>();
    dim3 g2(4, 32);                        // N=512, M=4096
    gemm_mma<1><<<g2, 256>>>(nullptr, Wo, nullptr, nullptr, bo, nullptr, nullptr, out);
}

// round 9
// speedup vs baseline: 2.5491x; 1.3406x over previous
#include <cuda_runtime.h>
#include <cuda_bf16.h>
#include <math.h>
#include <stdint.h>

// Problem constants (fixed shapes for this benchmark)
#define BSZ 2
#define LSEQ 2048
#define DMODEL 512
#define NHEAD 8
#define EDIM 64
#define NTOK 64
#define NVAR 32

// ---------------- scratch (device globals; no allocation allowed) ----------
__device__ float g_Q[BSZ * NHEAD * LSEQ * EDIM];   // [b][h][l][e]
__device__ float g_K[BSZ * NHEAD * LSEQ * EDIM];
__device__ float g_V[BSZ * NHEAD * LSEQ * EDIM];
__device__ float g_VO[BSZ * LSEQ * DMODEL];        // attention out, (B*L, D)
__device__ float g_part[BSZ * NHEAD * 32 * 64 * 64]; // partial accumulators
__device__ float g_ml[BSZ * NHEAD * 32 * 64 * 2];    // (m, l) per partial row

__device__ __forceinline__ uint32_t smem_u32(const void* p) {
    uint32_t a;
    asm("{ .reg .u64 t; cvta.to.shared.u64 t, %1; cvt.u32.u64 %0, t; }"
        : "=r"(a) : "l"(p));
    return a;
}

// SW128 swizzle at byte granularity (128B rows)
#define SWZ128(o) ((o) ^ (((o) >> 3) & 0x70))

// ============ bf16 hi/lo split GEMM via mma.sync (sm_80 PTX path) ===========
// C = Ah*Bh + Ah*Bl + Al*Bh + bias; hi/lo staged ONCE per K-chunk.
// MODE 0: QKV scatter (+fused RoPE on Q,K); MODE 1: out projection.
#define GBM 128
#define GBN 128
#define GBK 64
#define GSMEM (4 * 16384)   // Ah, Al, Bh, Bl
#define OFF_AH 0
#define OFF_AL 16384
#define OFF_BH 32768
#define OFF_BL 49152

// float4 -> bf16 hi into bufh, residual lo into bufl (8B each, swizzled)
__device__ __forceinline__ void stage_hilo(
    uint8_t* bufh, uint8_t* bufl, int row, int c4, float4 v)
{
    __nv_bfloat16 h0 = __float2bfloat16(v.x);
    __nv_bfloat16 h1 = __float2bfloat16(v.y);
    __nv_bfloat16 h2 = __float2bfloat16(v.z);
    __nv_bfloat16 h3 = __float2bfloat16(v.w);
    __nv_bfloat16 l0 = __float2bfloat16(v.x - __bfloat162float(h0));
    __nv_bfloat16 l1 = __float2bfloat16(v.y - __bfloat162float(h1));
    __nv_bfloat16 l2 = __float2bfloat16(v.z - __bfloat162float(h2));
    __nv_bfloat16 l3 = __float2bfloat16(v.w - __bfloat162float(h3));
    uint2 hp, lp;
    hp.x = (uint32_t)__bfloat16_as_ushort(h0) | ((uint32_t)__bfloat16_as_ushort(h1) << 16);
    hp.y = (uint32_t)__bfloat16_as_ushort(h2) | ((uint32_t)__bfloat16_as_ushort(h3) << 16);
    lp.x = (uint32_t)__bfloat16_as_ushort(l0) | ((uint32_t)__bfloat16_as_ushort(l1) << 16);
    lp.y = (uint32_t)__bfloat16_as_ushort(l2) | ((uint32_t)__bfloat16_as_ushort(l3) << 16);
    uint32_t off = SWZ128((uint32_t)(row * 128 + c4 * 2));
    *(uint2*)(bufh + off) = hp;
    *(uint2*)(bufl + off) = lp;
}

__device__ __forceinline__ void ldm_x4(uint32_t r[4], uint32_t addr)
{
    asm volatile("ldmatrix.sync.aligned.m8n8.x4.shared.b16 {%0,%1,%2,%3}, [%4];"
                 : "=r"(r[0]), "=r"(r[1]), "=r"(r[2]), "=r"(r[3]) : "r"(addr));
}

__device__ __forceinline__ void mma_16816(
    float c[4], const uint32_t a[4], uint32_t b0, uint32_t b1)
{
    asm volatile(
        "mma.sync.aligned.m16n8k16.row.col.f32.bf16.bf16.f32 "
        "{%0,%1,%2,%3}, {%4,%5,%6,%7}, {%8,%9}, {%0,%1,%2,%3};"
        : "+f"(c[0]), "+f"(c[1]), "+f"(c[2]), "+f"(c[3])
        : "r"(a[0]), "r"(a[1]), "r"(a[2]), "r"(a[3]), "r"(b0), "r"(b1));
}

template <int MODE>
__global__ __launch_bounds__(256) void gemm_mma(
    const float* __restrict__ A,
    const float* __restrict__ W0, const float* __restrict__ W1, const float* __restrict__ W2,
    const float* __restrict__ b0v, const float* __restrict__ b1v, const float* __restrict__ b2v,
    float* __restrict__ outp)
{
    extern __shared__ __align__(16) uint8_t smem[];

    const int tid = threadIdx.x;
    const int lane = tid & 31;
    const int warp = tid >> 5;
    const int warp_m = warp >> 2;        // 0..1  (64-row slab)
    const int warp_n = warp & 3;         // 0..3  (32-col slab)

    const int nt = blockIdx.x, mt = blockIdx.y;
    const int m0 = mt * GBM;
    const int which = (MODE == 0) ? (nt >> 2) : 0;
    const float* W    = (MODE == 0) ? ((which == 0) ? W0 : (which == 1) ? W1 : W2) : W0;
    const float* bias = (MODE == 0) ? ((which == 0) ? b0v : (which == 1) ? b1v : b2v) : b0v;
    const int wn0 = (MODE == 0) ? ((nt & 3) * GBN) : nt * GBN;
    const float* Asrc = (MODE == 0) ? A : g_VO;

    const uint32_t ah_b = smem_u32(smem + OFF_AH);
    const uint32_t al_b = smem_u32(smem + OFF_AL);
    const uint32_t bh_b = smem_u32(smem + OFF_BH);
    const uint32_t bl_b = smem_u32(smem + OFF_BL);

    float C[4][4][4];
#pragma unroll
    for (int i = 0; i < 4; i++)
#pragma unroll
        for (int j = 0; j < 4; j++)
#pragma unroll
            for (int q = 0; q < 4; q++) C[i][j][q] = 0.f;

    const int srow = tid >> 4;           // staging base row (16 rows per step)
    const int sc4  = (tid & 15) << 2;    // float4 col offset

    for (int cc = 0; cc < 8; cc++) {
        const int k0 = cc << 6;

        // ---- stage A and B chunk once: fp32 -> bf16 hi AND lo ----
#pragma unroll
        for (int it = 0; it < 8; it++) {
            int row = it * 16 + srow;
            float4 va = *(const float4*)(Asrc + (size_t)(m0 + row) * DMODEL + k0 + sc4);
            stage_hilo(smem + OFF_AH, smem + OFF_AL, row, sc4, va);
            float4 vb = *(const float4*)(W + (size_t)(wn0 + row) * DMODEL + k0 + sc4);
            stage_hilo(smem + OFF_BH, smem + OFF_BL, row, sc4, vb);
        }
        __syncthreads();

        // ---- compute: 4 k16 steps x 3 split terms ----
#pragma unroll
        for (int ks = 0; ks < 4; ks++) {
            const int kb = (ks * 16 + (lane >> 4) * 8) * 2;
            const int arow = warp_m * 64 + (lane & 15);
            const int brow = warp_n * 32 + (lane & 15);

            uint32_t af[4][4];
#pragma unroll
            for (int mf = 0; mf < 4; mf++)
                ldm_x4(af[mf], ah_b + SWZ128((uint32_t)((arow + mf * 16) * 128 + kb)));
            uint32_t bhf[2][4], blf[2][4];
#pragma unroll
            for (int np = 0; np < 2; np++) {
                ldm_x4(bhf[np], bh_b + SWZ128((uint32_t)((brow + np * 16) * 128 + kb)));
                ldm_x4(blf[np], bl_b + SWZ128((uint32_t)((brow + np * 16) * 128 + kb)));
            }
            // Ah*Bh and Ah*Bl
#pragma unroll
            for (int mf = 0; mf < 4; mf++)
#pragma unroll
                for (int np = 0; np < 2; np++) {
                    mma_16816(C[mf][np * 2 + 0], af[mf], bhf[np][0], bhf[np][2]);
                    mma_16816(C[mf][np * 2 + 1], af[mf], bhf[np][1], bhf[np][3]);
                    mma_16816(C[mf][np * 2 + 0], af[mf], blf[np][0], blf[np][2]);
                    mma_16816(C[mf][np * 2 + 1], af[mf], blf[np][1], blf[np][3]);
                }
            // Al*Bh (reload a-frags from lo buffer)
#pragma unroll
            for (int mf = 0; mf < 4; mf++)
                ldm_x4(af[mf], al_b + SWZ128((uint32_t)((arow + mf * 16) * 128 + kb)));
#pragma unroll
            for (int mf = 0; mf < 4; mf++)
#pragma unroll
                for (int np = 0; np < 2; np++) {
                    mma_16816(C[mf][np * 2 + 0], af[mf], bhf[np][0], bhf[np][2]);
                    mma_16816(C[mf][np * 2 + 1], af[mf], bhf[np][1], bhf[np][3]);
                }
        }
        __syncthreads();
    }

    // ---- epilogue: bias add (+ fused RoPE for Q,K) + store ----
    float* dst = (MODE == 0) ? ((which == 0) ? g_Q : (which == 1) ? g_K : g_V) : outp;
    const bool dorope = (MODE == 0) && (which < 2) && ((warp_n & 1) == 0);
#pragma unroll
    for (int mf = 0; mf < 4; mf++) {
#pragma unroll
        for (int nf = 0; nf < 4; nf++) {
            int colg = wn0 + warp_n * 32 + nf * 8 + (lane & 3) * 2;
            float bx = bias[colg], by = bias[colg + 1];
            int e = colg & 63;
            float theta = exp2f(-(float)(e >> 1) * 0.83048202372184f);
#pragma unroll
            for (int half = 0; half < 2; half++) {
                int m = m0 + warp_m * 64 + mf * 16 + (lane >> 2) + half * 8;
                float2 o;
                o.x = C[mf][nf][half * 2 + 0] + bx;
                o.y = C[mf][nf][half * 2 + 1] + by;
                if (MODE == 0) {
                    int bb = m >> 11, l = m & 2047;
                    if (dorope) {
                        float sv, cv;
                        sincosf((float)l * theta, &sv, &cv);
                        float nx = cv * o.x - sv * o.y;
                        float ny = cv * o.y + sv * o.x;
                        o.x = nx; o.y = ny;
                    }
                    int hh = colg >> 6;
                    *(float2*)&dst[(((size_t)bb * NHEAD + hh) * LSEQ + l) * EDIM + e] = o;
                } else {
                    *(float2*)&dst[(size_t)m * DMODEL + colg] = o;
                }
            }
        }
    }
}

// ---------------- attention: merged diag + last-rows kernel -----------------
#define STR 68   // smem row stride (floats)

__global__ __launch_bounds__(256) void attn_main(const float* __restrict__ be)
{
    __shared__ float Ash[64 * STR];   // phase1: Q^T [e][row]; phase2: P^T [c][row]
    __shared__ float Bsh[64 * STR];   // phase1: K^T [e][col]; phase2: V [c][e]

    const int bx = blockIdx.x;
    const int tid = threadIdx.x;

    int bb, h, qrow0, krow0, slot;
    bool diag;
    if (bx < 512) {
        int vb = bx & 31; h = (bx >> 5) & 7; bb = bx >> 8;
        qrow0 = vb * 64; krow0 = vb * 64; slot = vb; diag = true;
    } else {
        int y = bx - 512;
        int chunk = y % 31; int t2 = y / 31; h = t2 & 7; bb = t2 >> 3;
        qrow0 = LSEQ - 64; krow0 = chunk * 64; slot = chunk; diag = false;
    }
    const size_t bhbase = ((size_t)bb * NHEAD + h) * LSEQ;
    const float* Qg = g_Q + (bhbase + qrow0) * EDIM;
    const float* Kg = g_K + (bhbase + krow0) * EDIM;
    const float* Vg = g_V + (bhbase + krow0) * EDIM;

#pragma unroll
    for (int t = 0; t < 4; t++) {
        int idx = t * 256 + tid;
        int row = idx >> 4;
        int e0 = (idx & 15) << 2;
        float4 q = *(const float4*)(Qg + row * 64 + e0);
        float4 k = *(const float4*)(Kg + row * 64 + e0);
        Ash[(e0 + 0) * STR + row] = q.x; Ash[(e0 + 1) * STR + row] = q.y;
        Ash[(e0 + 2) * STR + row] = q.z; Ash[(e0 + 3) * STR + row] = q.w;
        Bsh[(e0 + 0) * STR + row] = k.x; Bsh[(e0 + 1) * STR + row] = k.y;
        Bsh[(e0 + 2) * STR + row] = k.z; Bsh[(e0 + 3) * STR + row] = k.w;
    }
    __syncthreads();

    const int ty = tid >> 4, tx = tid & 15;
    const int r0 = ty << 2, c0 = tx << 2;
    const float biasv = 0.125f * (diag ? be[NHEAD + h] : be[h]);

    float s[4][4];
#pragma unroll
    for (int i = 0; i < 4; i++)
#pragma unroll
        for (int j = 0; j < 4; j++) s[i][j] = 0.f;

#pragma unroll 8
    for (int e = 0; e < 64; e++) {
        float4 a4 = *(const float4*)&Ash[e * STR + r0];
        float4 b4 = *(const float4*)&Bsh[e * STR + c0];
        float a[4] = {a4.x, a4.y, a4.z, a4.w};
        float b[4] = {b4.x, b4.y, b4.z, b4.w};
#pragma unroll
        for (int i = 0; i < 4; i++)
#pragma unroll
            for (int j = 0; j < 4; j++)
                s[i][j] += a[i] * b[j];
    }

    float m[4], l[4];
#pragma unroll
    for (int i = 0; i < 4; i++) {
        float mm = -1e30f;
#pragma unroll
        for (int j = 0; j < 4; j++) {
            float v = 0.125f * s[i][j] + biasv;
            if (diag && (c0 + j > r0 + i)) v = -1e30f;
            s[i][j] = v;
            mm = fmaxf(mm, v);
        }
        mm = fmaxf(mm, __shfl_xor_sync(0xffffffffu, mm, 1));
        mm = fmaxf(mm, __shfl_xor_sync(0xffffffffu, mm, 2));
        mm = fmaxf(mm, __shfl_xor_sync(0xffffffffu, mm, 4));
        mm = fmaxf(mm, __shfl_xor_sync(0xffffffffu, mm, 8));
        m[i] = mm;
        float ls = 0.f;
#pragma unroll
        for (int j = 0; j < 4; j++) {
            float p = __expf(s[i][j] - mm);
            s[i][j] = p;
            ls += p;
        }
        ls += __shfl_xor_sync(0xffffffffu, ls, 1);
        ls += __shfl_xor_sync(0xffffffffu, ls, 2);
        ls += __shfl_xor_sync(0xffffffffu, ls, 4);
        ls += __shfl_xor_sync(0xffffffffu, ls, 8);
        l[i] = ls;
    }

    __syncthreads();

#pragma unroll
    for (int i = 0; i < 4; i++)
#pragma unroll
        for (int j = 0; j < 4; j++)
            Ash[(c0 + j) * STR + r0 + i] = s[i][j];
#pragma unroll
    for (int t = 0; t < 4; t++) {
        int idx = t * 256 + tid;
        int c = idx >> 4;
        int e0 = (idx & 15) << 2;
        *(float4*)&Bsh[c * STR + e0] = *(const float4*)(Vg + c * 64 + e0);
    }
    __syncthreads();

    float o[4][4];
#pragma unroll
    for (int i = 0; i < 4; i++)
#pragma unroll
        for (int j = 0; j < 4; j++) o[i][j] = 0.f;

#pragma unroll 8
    for (int c = 0; c < 64; c++) {
        float4 a4 = *(const float4*)&Ash[c * STR + r0];
        float4 b4 = *(const float4*)&Bsh[c * STR + c0];
        float a[4] = {a4.x, a4.y, a4.z, a4.w};
        float b[4] = {b4.x, b4.y, b4.z, b4.w};
#pragma unroll
        for (int i = 0; i < 4; i++)
#pragma unroll
            for (int j = 0; j < 4; j++)
                o[i][j] += a[i] * b[j];
    }

    if (diag && slot < 31) {
#pragma unroll
        for (int i = 0; i < 4; i++) {
            float inv = 1.f / l[i];
            int ll = qrow0 + r0 + i;
            float4 w;
            w.x = o[i][0] * inv; w.y = o[i][1] * inv;
            w.z = o[i][2] * inv; w.w = o[i][3] * inv;
            *(float4*)&g_VO[((size_t)bb * LSEQ + ll) * DMODEL + h * 64 + c0] = w;
        }
    } else {
        size_t bh = (size_t)bb * NHEAD + h;
#pragma unroll
        for (int i = 0; i < 4; i++) {
            float4 w;
            w.x = o[i][0]; w.y = o[i][1]; w.z = o[i][2]; w.w = o[i][3];
            *(float4*)&g_part[(((bh * 32 + slot) * 64) + r0 + i) * 64 + c0] = w;
            if (tx == 0) {
                size_t mb = (((bh * 32 + slot) * 64) + r0 + i) * 2;
                g_ml[mb] = m[i]; g_ml[mb + 1] = l[i];
            }
        }
    }
}

// ---------------- attention: merge partials (1024 CTAs, 1 row each) --------
__global__ __launch_bounds__(256) void attn_merge()
{
    __shared__ float sw[32];
    __shared__ float sinvs;
    __shared__ float red[4][64];

    const int bx = blockIdx.x;          // 0..1023
    const int bh = bx >> 6;
    const int r  = bx & 63;
    const int tid = threadIdx.x;

    if (tid < 32) {
        int c = tid;
        size_t mb = (((size_t)bh * 32 + c) * 64 + r) * 2;
        float mi = g_ml[mb];
        float li = g_ml[mb + 1];
        float mv = mi;
#pragma unroll
        for (int o = 16; o; o >>= 1) mv = fmaxf(mv, __shfl_xor_sync(0xffffffffu, mv, o));
        float w = __expf(mi - mv);
        float lw = w * li;
#pragma unroll
        for (int o = 16; o; o >>= 1) lw += __shfl_xor_sync(0xffffffffu, lw, o);
        sw[c] = w;
        if (c == 0) sinvs = 1.f / lw;
    }
    __syncthreads();

    const int e = tid & 63, cg = tid >> 6;
    float acc = 0.f;
#pragma unroll
    for (int cq = 0; cq < 8; cq++) {
        int c = cg * 8 + cq;
        acc += sw[c] * g_part[(((size_t)bh * 32 + c) * 64 + r) * 64 + e];
    }
    red[cg][e] = acc;
    __syncthreads();

    if (tid < 64) {
        float s = red[0][tid] + red[1][tid] + red[2][tid] + red[3][tid];
        int bb = bh >> 3, h = bh & 7;
        g_VO[((size_t)bb * LSEQ + (LSEQ - 64 + r)) * DMODEL + h * 64 + tid] = s * sinvs;
    }
}

// ---------------- launch ----------------------------------------------------
extern "C" void kernel_launch(void* const* d_in, const int* in_sizes, int n_in,
                              void* d_out, int out_size)
{
    (void)in_sizes; (void)n_in; (void)out_size;
    const float* x   = (const float*)d_in[0];
    const float* Wq  = (const float*)d_in[1];
    const float* bq  = (const float*)d_in[2];
    const float* Wk  = (const float*)d_in[3];
    const float* bk  = (const float*)d_in[4];
    const float* Wv  = (const float*)d_in[5];
    const float* bv  = (const float*)d_in[6];
    const float* Wo  = (const float*)d_in[7];
    const float* bo  = (const float*)d_in[8];
    const float* be  = (const float*)d_in[9];
    float* out = (float*)d_out;

    cudaFuncSetAttribute(gemm_mma<0>, cudaFuncAttributeMaxDynamicSharedMemorySize, GSMEM);
    cudaFuncSetAttribute(gemm_mma<1>, cudaFuncAttributeMaxDynamicSharedMemorySize, GSMEM);

    dim3 g1(12, 32);                       // N=1536 (3 x 512), M=4096
    gemm_mma<0><<<g1, 256, GSMEM>>>(x, Wq, Wk, Wv, bq, bk, bv, nullptr);
    attn_main<<<512 + BSZ * NHEAD * 31, 256>>>(be);
    attn_merge<<<1024, 256>>>();
    dim3 g2(4, 32);                        // N=512, M=4096
    gemm_mma<1><<<g2, 256, GSMEM>>>(nullptr, Wo, nullptr, nullptr, bo, nullptr, nullptr, out);
}